// round 1
// baseline (speedup 1.0000x reference)
#include <cuda_runtime.h>
#include <cuda_bf16.h>
#include <cstdint>

// Problem dims
#define BATCH 32
#define TLEN  2048
#define IDIM  512
#define HEADS 16
#define DDIM  64
#define MROWS (BATCH * TLEN)      // 65536
#define NCOLS (HEADS * DDIM)      // 1024 per c-slice

// Scratch (device globals; allocation-free)
__device__ float g_wp[3ull * IDIM * NCOLS];            // permuted weights: [c][i][h*64+d]  (6 MB)
__device__ float g_proj[3ull * MROWS * NCOLS];         // k,v,q projections [c][m][h*64+d]  (768 MB)
__device__ float g_s[(size_t)BATCH * HEADS * TLEN];    // scores [bh][t]                    (4 MB)
__device__ float g_ht[(size_t)BATCH * HEADS * TLEN * DDIM]; // per-head outputs [bh][t][d]  (256 MB)

// ---------------------------------------------------------------------------
// K0: permute W (I,H,D,3) -> Wp[c][i][h*64+d]
// ---------------------------------------------------------------------------
__global__ void permute_w_kernel(const float* __restrict__ W) {
    size_t e = (size_t)blockIdx.x * blockDim.x + threadIdx.x;
    const size_t total = 3ull * IDIM * NCOLS;
    if (e >= total) return;
    int c = (int)(e / (IDIM * NCOLS));
    int r = (int)(e % (IDIM * NCOLS));
    int i = r >> 10;          // / 1024
    int j = r & 1023;
    int h = j >> 6;
    int d = j & 63;
    g_wp[e] = W[(size_t)i * (HEADS * DDIM * 3) + h * (DDIM * 3) + d * 3 + c];
}

// ---------------------------------------------------------------------------
// K1: SGEMM  C_c[m][n] = sum_k X[m][k] * Wp[c][k][n]
//     BM=128 BN=128 BK=8, 256 threads, 8x8 microtile, double-buffered smem
// ---------------------------------------------------------------------------
__global__ __launch_bounds__(256) void sgemm_kernel(const float* __restrict__ A) {
    const int c = blockIdx.z;
    const float* __restrict__ B = g_wp + (size_t)c * IDIM * NCOLS;
    float* __restrict__ C = g_proj + (size_t)c * MROWS * NCOLS;

    const int bn = blockIdx.x * 128;
    const int bm = blockIdx.y * 128;
    const int tid = threadIdx.x;

    __shared__ float As[2][8][128];
    __shared__ float Bs[2][8][128];

    // A loads: 128 rows x 8 k = 256 float4; thread -> (row = tid/2, kcol = (tid&1)*4)
    const int arow = tid >> 1;
    const int acol = (tid & 1) * 4;
    // B loads: 8 rows x 128 n = 256 float4; thread -> (krow = tid/32, ncol = (tid&31)*4)
    const int brow = tid >> 5;
    const int bcol = (tid & 31) * 4;

    const float* Aptr = A + (size_t)(bm + arow) * IDIM + acol;
    const float* Bptr = B + (size_t)brow * NCOLS + bn + bcol;

    // preload tile 0
    float4 a0 = *(const float4*)(Aptr);
    float4 b0 = *(const float4*)(Bptr);
    As[0][acol + 0][arow] = a0.x;
    As[0][acol + 1][arow] = a0.y;
    As[0][acol + 2][arow] = a0.z;
    As[0][acol + 3][arow] = a0.w;
    *(float4*)&Bs[0][brow][bcol] = b0;
    __syncthreads();

    float acc[8][8];
#pragma unroll
    for (int i = 0; i < 8; i++)
#pragma unroll
        for (int j = 0; j < 8; j++) acc[i][j] = 0.0f;

    const int ty = (tid >> 4) * 8;  // m offset within tile
    const int tx = (tid & 15) * 8;  // n offset within tile

    int cur = 0;
    const int KT = IDIM / 8;  // 64
#pragma unroll 1
    for (int kt = 0; kt < KT; ++kt) {
        float4 an, bnx;
        if (kt < KT - 1) {
            an  = *(const float4*)(Aptr + (kt + 1) * 8);
            bnx = *(const float4*)(Bptr + (size_t)(kt + 1) * 8 * NCOLS);
        }
#pragma unroll
        for (int kk = 0; kk < 8; ++kk) {
            float af[8], bf[8];
            *(float4*)&af[0] = *(const float4*)&As[cur][kk][ty];
            *(float4*)&af[4] = *(const float4*)&As[cur][kk][ty + 4];
            *(float4*)&bf[0] = *(const float4*)&Bs[cur][kk][tx];
            *(float4*)&bf[4] = *(const float4*)&Bs[cur][kk][tx + 4];
#pragma unroll
            for (int i = 0; i < 8; i++)
#pragma unroll
                for (int j = 0; j < 8; j++)
                    acc[i][j] = fmaf(af[i], bf[j], acc[i][j]);
        }
        if (kt < KT - 1) {
            int nxt = cur ^ 1;
            As[nxt][acol + 0][arow] = an.x;
            As[nxt][acol + 1][arow] = an.y;
            As[nxt][acol + 2][arow] = an.z;
            As[nxt][acol + 3][arow] = an.w;
            *(float4*)&Bs[nxt][brow][bcol] = bnx;
            cur = nxt;
        }
        __syncthreads();
    }

    float* Cp = C + (size_t)(bm + ty) * NCOLS + bn + tx;
#pragma unroll
    for (int i = 0; i < 8; i++) {
        *(float4*)(Cp + (size_t)i * NCOLS)     = make_float4(acc[i][0], acc[i][1], acc[i][2], acc[i][3]);
        *(float4*)(Cp + (size_t)i * NCOLS + 4) = make_float4(acc[i][4], acc[i][5], acc[i][6], acc[i][7]);
    }
}

// ---------------------------------------------------------------------------
// K2: scores  s[bh][t] = sum_d q[m][h*64+d] * k[m][h*64+d]
// ---------------------------------------------------------------------------
__global__ void scores_kernel() {
    size_t idx = (size_t)blockIdx.x * blockDim.x + threadIdx.x;  // over MROWS*HEADS
    if (idx >= (size_t)MROWS * HEADS) return;
    int m = (int)(idx >> 4);
    int h = (int)(idx & 15);
    const float* kb = g_proj + (size_t)0 * MROWS * NCOLS + (size_t)m * NCOLS + h * DDIM;
    const float* qb = g_proj + (size_t)2 * MROWS * NCOLS + (size_t)m * NCOLS + h * DDIM;
    float acc = 0.0f;
#pragma unroll
    for (int i = 0; i < DDIM / 4; i++) {
        float4 qv = ((const float4*)qb)[i];
        float4 kv = ((const float4*)kb)[i];
        acc += qv.x * kv.x + qv.y * kv.y + qv.z * kv.z + qv.w * kv.w;
    }
    int b = m >> 11;         // / TLEN
    int t = m & (TLEN - 1);
    g_s[((size_t)(b * HEADS + h)) * TLEN + t] = acc;
}

// ---------------------------------------------------------------------------
// K3: scan — one warp per (b,h) chain; each lane owns 2 d's.
//     Carry chain per step: max -> exp -> fma -> rcp. Inputs prefetched.
// ---------------------------------------------------------------------------
__global__ __launch_bounds__(32) void scan_kernel() {
    const int bh = blockIdx.x;        // 0..511
    const int b = bh >> 4, h = bh & 15;
    const int lane = threadIdx.x;

    const float* __restrict__ vbase =
        g_proj + (size_t)1 * MROWS * NCOLS + (size_t)b * TLEN * NCOLS + h * DDIM + 2 * lane;
    const float* __restrict__ sbase = g_s + (size_t)bh * TLEN;
    float* __restrict__ obase = g_ht + (size_t)bh * TLEN * DDIM + 2 * lane;

    float2 num = make_float2(0.0f, 0.0f);
    float den = 0.0f, mx = 0.0f;

    float2 vcur = *(const float2*)(vbase);
    float scur = sbase[0];

    for (int t = 0; t < TLEN; ++t) {
        float2 vnext = vcur;
        float snext = scur;
        if (t < TLEN - 1) {
            vnext = *(const float2*)(vbase + (size_t)(t + 1) * NCOLS);
            snext = sbase[t + 1];
        }
        float nmx = fmaxf(mx, scur);
        float md = __expf(mx - nmx);
        float sm = __expf(scur - nmx);
        den = fmaf(den, md, sm);
        num.x = fmaf(num.x, md, vcur.x * sm);
        num.y = fmaf(num.y, md, vcur.y * sm);
        float inv = 1.0f / den;
        *(float2*)(obase + (size_t)t * DDIM) = make_float2(num.x * inv, num.y * inv);
        mx = nmx;
        vcur = vnext;
        scur = snext;
    }
}

// ---------------------------------------------------------------------------
// K4: cross-head reduce  out[b][t][d] = sum_h ht[bh][t][d]
// ---------------------------------------------------------------------------
__global__ void reduce_kernel(float* __restrict__ out) {
    size_t idx = (size_t)blockIdx.x * blockDim.x + threadIdx.x;  // over MROWS * 16 float4-groups
    if (idx >= (size_t)MROWS * (DDIM / 4)) return;
    int m = (int)(idx >> 4);
    int d4 = (int)(idx & 15);
    int b = m >> 11;
    int t = m & (TLEN - 1);
    const float* base = g_ht + ((size_t)(b * HEADS) * TLEN + t) * DDIM + d4 * 4;
    float4 acc = make_float4(0.0f, 0.0f, 0.0f, 0.0f);
#pragma unroll
    for (int h = 0; h < HEADS; h++) {
        float4 x = *(const float4*)(base + (size_t)h * TLEN * DDIM);
        acc.x += x.x; acc.y += x.y; acc.z += x.z; acc.w += x.w;
    }
    ((float4*)out)[idx] = acc;
}

// ---------------------------------------------------------------------------
extern "C" void kernel_launch(void* const* d_in, const int* in_sizes, int n_in,
                              void* d_out, int out_size) {
    const float* x = (const float*)d_in[0];
    const float* w = (const float*)d_in[1];
    // defensive: identify by size (x = 33554432, W = 1572864)
    if (n_in >= 2 && in_sizes[0] == IDIM * HEADS * DDIM * 3) {
        const float* tmp = x; x = w; w = tmp;
    }
    float* out = (float*)d_out;

    {   // K0: permute weights
        const size_t total = 3ull * IDIM * NCOLS;
        permute_w_kernel<<<(unsigned)((total + 255) / 256), 256>>>(w);
    }
    {   // K1: projection GEMM (3 x 65536x512x1024)
        dim3 grid(NCOLS / 128, MROWS / 128, 3);
        sgemm_kernel<<<grid, 256>>>(x);
    }
    {   // K2: scores
        const size_t total = (size_t)MROWS * HEADS;
        scores_kernel<<<(unsigned)((total + 127) / 128), 128>>>();
    }
    {   // K3: scan (one warp per (b,h))
        scan_kernel<<<BATCH * HEADS, 32>>>();
    }
    {   // K4: head reduction
        const size_t total = (size_t)MROWS * (DDIM / 4);
        reduce_kernel<<<(unsigned)((total + 127) / 128), 128>>>(out);
    }
}

// round 3
// speedup vs baseline: 2.1072x; 2.1072x over previous
#include <cuda_runtime.h>
#include <cuda_bf16.h>
#include <cstdint>

// Problem dims
#define BATCH 32
#define TLEN  2048
#define IDIM  512
#define HEADS 16
#define DDIM  64
#define MROWS (BATCH * TLEN)      // 65536
#define NCOLS (HEADS * DDIM)      // 1024 per c-slice
#define KTOT  1536                // 3 * IDIM (bf16 hi/lo split GEMM)

// GEMM tiling (mma.sync path — family-portable, no tcgen05 on this compile target)
#define BM 128
#define BN 128
#define BK 32
#define NT (KTOT / BK)            // 48
#define STAGES 4
#define ROWB 80                   // smem row stride bytes: 32*2 + 16 pad (conflict-free ldmatrix)
#define STAGE_BYTES (128 * ROWB)  // 10240
#define SMEM_TOTAL (2 * STAGES * STAGE_BYTES)  // 81920

// Scratch (device globals; allocation-free)
__device__ __nv_bfloat16 g_xs[(size_t)MROWS * KTOT];            // 192 MB split-X [m][k]
__device__ __nv_bfloat16 g_ws[3ull * NCOLS * KTOT];             // 9 MB split-W [c][n][k]
__device__ float g_proj[3ull * MROWS * NCOLS];                  // 768 MB [c][m][n]
__device__ float g_s[(size_t)BATCH * HEADS * TLEN];             // 4 MB scores [bh][t]
__device__ float g_ht[(size_t)BATCH * HEADS * TLEN * DDIM];     // 256 MB [bh][t][d]

// ---------------------------------------------------------------------------
// PTX helpers (sm_80-era, family-portable)
// ---------------------------------------------------------------------------
__device__ __forceinline__ uint32_t smem_u32(const void* p) {
    uint32_t a;
    asm("{ .reg .u64 t; cvta.to.shared.u64 t, %1; cvt.u32.u64 %0, t; }" : "=r"(a) : "l"(p));
    return a;
}
__device__ __forceinline__ void cp_async16(uint32_t dst, const void* src) {
    asm volatile("cp.async.cg.shared.global [%0], [%1], 16;" :: "r"(dst), "l"(src));
}
__device__ __forceinline__ void cp_commit() { asm volatile("cp.async.commit_group;" ::: "memory"); }
__device__ __forceinline__ void cp_wait2()  { asm volatile("cp.async.wait_group 2;" ::: "memory"); }

__device__ __forceinline__ void ldsm_x4(uint32_t* r, uint32_t addr) {
    asm volatile("ldmatrix.sync.aligned.m8n8.x4.shared.b16 {%0,%1,%2,%3}, [%4];"
                 : "=r"(r[0]), "=r"(r[1]), "=r"(r[2]), "=r"(r[3]) : "r"(addr));
}
__device__ __forceinline__ void mma16816(float* c, const uint32_t* a, uint32_t b0, uint32_t b1) {
    asm volatile("mma.sync.aligned.m16n8k16.row.col.f32.bf16.bf16.f32 "
                 "{%0,%1,%2,%3}, {%4,%5,%6,%7}, {%8,%9}, {%0,%1,%2,%3};"
                 : "+f"(c[0]), "+f"(c[1]), "+f"(c[2]), "+f"(c[3])
                 : "r"(a[0]), "r"(a[1]), "r"(a[2]), "r"(a[3]), "r"(b0), "r"(b1));
}

// ---------------------------------------------------------------------------
// K0a: split X -> bf16 blocks: Xs[m][0:512)=hi, [512:1024)=lo, [1024:1536)=hi
// ---------------------------------------------------------------------------
__global__ void convx_kernel(const float* __restrict__ x) {
    size_t e = (size_t)blockIdx.x * blockDim.x + threadIdx.x;
    if (e >= (size_t)MROWS * IDIM) return;
    size_t m = e >> 9;
    int k = (int)(e & 511);
    float v = x[e];
    __nv_bfloat16 hi = __float2bfloat16(v);
    __nv_bfloat16 lo = __float2bfloat16(v - __bfloat162float(hi));
    __nv_bfloat16* row = g_xs + m * KTOT;
    row[k] = hi;
    row[512 + k] = lo;
    row[1024 + k] = hi;
}

// ---------------------------------------------------------------------------
// K0b: split W -> Ws[c][n][0:512)=hi, [512:1024)=hi, [1024:1536)=lo
// ---------------------------------------------------------------------------
__global__ void convw_kernel(const float* __restrict__ W) {
    size_t e = (size_t)blockIdx.x * blockDim.x + threadIdx.x;
    if (e >= 3ull * IDIM * NCOLS) return;
    int c = (int)(e / (IDIM * NCOLS));
    int r = (int)(e % (IDIM * NCOLS));
    int k = r >> 10;
    int n = r & 1023;
    int h = n >> 6, d = n & 63;
    float v = W[(size_t)k * (HEADS * DDIM * 3) + h * (DDIM * 3) + d * 3 + c];
    __nv_bfloat16 hi = __float2bfloat16(v);
    __nv_bfloat16 lo = __float2bfloat16(v - __bfloat162float(hi));
    __nv_bfloat16* base = g_ws + ((size_t)c * NCOLS + n) * KTOT;
    base[k] = hi;
    base[512 + k] = hi;
    base[1024 + k] = lo;
}

// ---------------------------------------------------------------------------
// K1: bf16 mma.sync GEMM  C_c[m][n] = sum_k Xs[m][k] * Ws[c][n][k]
//     128x128x32 CTA tile, 4-stage cp.async, 8 warps (4m x 2n), 32x64 warp tile
// ---------------------------------------------------------------------------
__global__ __launch_bounds__(256, 2) void gemm_mma_kernel() {
    extern __shared__ char smem[];
    const int tid = threadIdx.x;
    const int wid = tid >> 5;
    const int lane = tid & 31;

    const int cslice = blockIdx.x >> 3;          // 0..2
    const int bn = (blockIdx.x & 7) * BN;        // 0..896
    const int bm = blockIdx.y * BM;
    const int wm = wid & 3;                      // warp m index (4)
    const int wn = wid >> 2;                     // warp n index (2)

    const uint32_t sb = smem_u32(smem);

    const __nv_bfloat16* __restrict__ Ag = g_xs + (size_t)bm * KTOT;
    const __nv_bfloat16* __restrict__ Bg = g_ws + ((size_t)cslice * NCOLS + bn) * KTOT;

    // per-thread load coords (2 x 16B chunks per tile per matrix)
    const int lrow0 = (tid)       >> 2, lcc0 = (tid)       & 3;
    const int lrow1 = (tid + 256) >> 2, lcc1 = (tid + 256) & 3;

    auto load_tile = [&](int kt, int s) {
        uint32_t as = sb + s * STAGE_BYTES;
        uint32_t bs = sb + (STAGES + s) * STAGE_BYTES;
        const __nv_bfloat16* ak = Ag + kt * BK;
        const __nv_bfloat16* bk = Bg + kt * BK;
        cp_async16(as + lrow0 * ROWB + lcc0 * 16, ak + (size_t)lrow0 * KTOT + lcc0 * 8);
        cp_async16(as + lrow1 * ROWB + lcc1 * 16, ak + (size_t)lrow1 * KTOT + lcc1 * 8);
        cp_async16(bs + lrow0 * ROWB + lcc0 * 16, bk + (size_t)lrow0 * KTOT + lcc0 * 8);
        cp_async16(bs + lrow1 * ROWB + lcc1 * 16, bk + (size_t)lrow1 * KTOT + lcc1 * 8);
        cp_commit();
    };

    // prologue: stages 0..2
    load_tile(0, 0);
    load_tile(1, 1);
    load_tile(2, 2);

    float acc[2][8][4];
#pragma unroll
    for (int mi = 0; mi < 2; mi++)
#pragma unroll
        for (int j = 0; j < 8; j++)
#pragma unroll
            for (int q = 0; q < 4; q++) acc[mi][j][q] = 0.0f;

    // ldmatrix per-lane addressing
    const int a_row  = wm * 32 + (lane & 15);
    const int a_byte = (lane >> 4) * 16;
    const int b_row  = wn * 64 + ((lane & 16) >> 1) + (lane & 7);
    const int b_byte = ((lane >> 3) & 1) * 16;

    for (int kt = 0; kt < NT; ++kt) {
        cp_wait2();
        __syncthreads();

        int nx = kt + STAGES - 1;
        if (nx < NT) load_tile(nx, nx % STAGES);
        else cp_commit();   // keep group counting uniform

        const int s = kt % STAGES;
        const uint32_t as = sb + s * STAGE_BYTES;
        const uint32_t bs = sb + (STAGES + s) * STAGE_BYTES;

#pragma unroll
        for (int ks = 0; ks < 2; ++ks) {
            uint32_t a[2][4], b[4][4];
            ldsm_x4(a[0], as + (a_row)      * ROWB + ks * 32 + a_byte);
            ldsm_x4(a[1], as + (a_row + 16) * ROWB + ks * 32 + a_byte);
#pragma unroll
            for (int jp = 0; jp < 4; jp++)
                ldsm_x4(b[jp], bs + (b_row + jp * 16) * ROWB + ks * 32 + b_byte);
#pragma unroll
            for (int mi = 0; mi < 2; mi++)
#pragma unroll
                for (int j = 0; j < 8; j++)
                    mma16816(acc[mi][j], a[mi], b[j >> 1][(j & 1) * 2], b[j >> 1][(j & 1) * 2 + 1]);
        }
    }

    // epilogue: write fp32 C
    float* __restrict__ Cc = g_proj + (size_t)cslice * MROWS * NCOLS;
    const int tr = lane >> 2;       // 0..7
    const int tc = (lane & 3) * 2;  // 0,2,4,6
#pragma unroll
    for (int mi = 0; mi < 2; mi++) {
        int row0 = bm + wm * 32 + mi * 16 + tr;
#pragma unroll
        for (int j = 0; j < 8; j++) {
            int col = bn + wn * 64 + j * 8 + tc;
            *(float2*)(Cc + (size_t)row0 * NCOLS + col)       = make_float2(acc[mi][j][0], acc[mi][j][1]);
            *(float2*)(Cc + (size_t)(row0 + 8) * NCOLS + col) = make_float2(acc[mi][j][2], acc[mi][j][3]);
        }
    }
}

// ---------------------------------------------------------------------------
// K2: scores  s[bh][t] = sum_d q . k
// ---------------------------------------------------------------------------
__global__ void scores_kernel() {
    size_t idx = (size_t)blockIdx.x * blockDim.x + threadIdx.x;
    if (idx >= (size_t)MROWS * HEADS) return;
    int m = (int)(idx >> 4);
    int h = (int)(idx & 15);
    const float* kb = g_proj + (size_t)0 * MROWS * NCOLS + (size_t)m * NCOLS + h * DDIM;
    const float* qb = g_proj + (size_t)2 * MROWS * NCOLS + (size_t)m * NCOLS + h * DDIM;
    float acc = 0.0f;
#pragma unroll
    for (int i = 0; i < DDIM / 4; i++) {
        float4 qv = ((const float4*)qb)[i];
        float4 kv = ((const float4*)kb)[i];
        acc += qv.x * kv.x + qv.y * kv.y + qv.z * kv.z + qv.w * kv.w;
    }
    int b = m >> 11;
    int t = m & (TLEN - 1);
    g_s[((size_t)(b * HEADS + h)) * TLEN + t] = acc;
}

// ---------------------------------------------------------------------------
// K3: scan — one warp per (b,h); prefetch ring depth 8 (MLP fix)
// ---------------------------------------------------------------------------
__global__ __launch_bounds__(32) void scan_kernel() {
    const int bh = blockIdx.x;
    const int b = bh >> 4, h = bh & 15;
    const int lane = threadIdx.x;

    const float* __restrict__ vbase =
        g_proj + (size_t)1 * MROWS * NCOLS + (size_t)b * TLEN * NCOLS + h * DDIM + 2 * lane;
    const float* __restrict__ sbase = g_s + (size_t)bh * TLEN;
    float* __restrict__ obase = g_ht + (size_t)bh * TLEN * DDIM + 2 * lane;

    float2 num = make_float2(0.0f, 0.0f);
    float den = 0.0f, mx = 0.0f;

    constexpr int PF = 8;
    float2 vbuf[PF];
    float sbuf[PF];
#pragma unroll
    for (int i = 0; i < PF; i++) {
        vbuf[i] = *(const float2*)(vbase + (size_t)i * NCOLS);
        sbuf[i] = sbase[i];
    }

    for (int t0 = 0; t0 < TLEN; t0 += PF) {
#pragma unroll
        for (int i = 0; i < PF; i++) {
            int t = t0 + i;
            float2 vc = vbuf[i];
            float sc = sbuf[i];
            int tp = t + PF;
            if (tp < TLEN) {
                vbuf[i] = *(const float2*)(vbase + (size_t)tp * NCOLS);
                sbuf[i] = sbase[tp];
            }
            float nmx = fmaxf(mx, sc);
            float md = __expf(mx - nmx);
            float sm = __expf(sc - nmx);
            den = fmaf(den, md, sm);
            num.x = fmaf(num.x, md, vc.x * sm);
            num.y = fmaf(num.y, md, vc.y * sm);
            float inv = 1.0f / den;
            *(float2*)(obase + (size_t)t * DDIM) = make_float2(num.x * inv, num.y * inv);
            mx = nmx;
        }
    }
}

// ---------------------------------------------------------------------------
// K4: cross-head reduce  out[b][t][d] = sum_h ht[bh][t][d]
// ---------------------------------------------------------------------------
__global__ void reduce_kernel(float* __restrict__ out) {
    size_t idx = (size_t)blockIdx.x * blockDim.x + threadIdx.x;
    if (idx >= (size_t)MROWS * (DDIM / 4)) return;
    int m = (int)(idx >> 4);
    int d4 = (int)(idx & 15);
    int b = m >> 11;
    int t = m & (TLEN - 1);
    const float* base = g_ht + ((size_t)(b * HEADS) * TLEN + t) * DDIM + d4 * 4;
    float4 acc = make_float4(0.0f, 0.0f, 0.0f, 0.0f);
#pragma unroll
    for (int h = 0; h < HEADS; h++) {
        float4 x = *(const float4*)(base + (size_t)h * TLEN * DDIM);
        acc.x += x.x; acc.y += x.y; acc.z += x.z; acc.w += x.w;
    }
    ((float4*)out)[idx] = acc;
}

// ---------------------------------------------------------------------------
extern "C" void kernel_launch(void* const* d_in, const int* in_sizes, int n_in,
                              void* d_out, int out_size) {
    const float* x = (const float*)d_in[0];
    const float* w = (const float*)d_in[1];
    if (n_in >= 2 && in_sizes[0] == IDIM * HEADS * DDIM * 3) {
        const float* tmp = x; x = w; w = tmp;
    }
    float* out = (float*)d_out;

    {   // split conversions
        size_t tx = (size_t)MROWS * IDIM;
        convx_kernel<<<(unsigned)((tx + 255) / 256), 256>>>(x);
        size_t tw = 3ull * IDIM * NCOLS;
        convw_kernel<<<(unsigned)((tw + 255) / 256), 256>>>(w);
    }
    {   // bf16 tensor-core GEMM (3 x 65536x512x1024, K tripled by hi/lo split)
        cudaFuncSetAttribute(gemm_mma_kernel, cudaFuncAttributeMaxDynamicSharedMemorySize, SMEM_TOTAL);
        dim3 grid(24, MROWS / BM);   // x = (c, nb), y = m-block
        gemm_mma_kernel<<<grid, 256, SMEM_TOTAL>>>();
    }
    {   // scores
        size_t total = (size_t)MROWS * HEADS;
        scores_kernel<<<(unsigned)((total + 127) / 128), 128>>>();
    }
    {   // scan
        scan_kernel<<<BATCH * HEADS, 32>>>();
    }
    {   // head reduction
        size_t total = (size_t)MROWS * (DDIM / 4);
        reduce_kernel<<<(unsigned)((total + 127) / 128), 128>>>(out);
    }
}